// round 1
// baseline (speedup 1.0000x reference)
#include <cuda_runtime.h>
#include <math.h>

#define NN 50000
#define EE 600000
#define HH 128

// ---------------- static device scratch (no allocs allowed) ----------------
__device__ float g_h[NN * HH];      // current node features
__device__ float g_hw[NN * HH];     // h @ W
__device__ float g_as[NN * 8];      // alpha_src per node/head
__device__ float g_ad[NN * 8];      // alpha_dst per node/head
__device__ int   g_cnt[NN];
__device__ int   g_incl[NN];
__device__ int   g_rowoff[NN + 1];
__device__ int   g_cursor[NN];
__device__ int   g_bsum[128];
__device__ int   g_bofs[128];
__device__ int   g_csr[EE];

// ---------------- input projection: h = x @ W_in + b_in --------------------
__global__ void input_proj(const float* __restrict__ x,
                           const float* __restrict__ W_in,
                           const float* __restrict__ b_in) {
    int idx = blockIdx.x * blockDim.x + threadIdx.x;
    if (idx >= NN * HH) return;
    int n = idx >> 7, j = idx & 127;
    g_h[idx] = x[n * 2] * W_in[j] + x[n * 2 + 1] * W_in[128 + j] + b_in[j];
}

// ---------------- CSR build -------------------------------------------------
__global__ void zero_cnt() {
    int i = blockIdx.x * blockDim.x + threadIdx.x;
    if (i < NN) g_cnt[i] = 0;
}
__global__ void count_kernel(const int* __restrict__ dst) {
    int e = blockIdx.x * blockDim.x + threadIdx.x;
    if (e < EE) atomicAdd(&g_cnt[dst[e]], 1);
}
__global__ void scan1() {
    __shared__ int sm[512];
    int i = blockIdx.x * 512 + threadIdx.x;
    int v = (i < NN) ? g_cnt[i] : 0;
    sm[threadIdx.x] = v;
    __syncthreads();
    for (int off = 1; off < 512; off <<= 1) {
        int t = (threadIdx.x >= off) ? sm[threadIdx.x - off] : 0;
        __syncthreads();
        sm[threadIdx.x] += t;
        __syncthreads();
    }
    if (i < NN) g_incl[i] = sm[threadIdx.x];
    if (threadIdx.x == 511) g_bsum[blockIdx.x] = sm[511];
}
__global__ void scan2(int nch) {
    __shared__ int sm[128];
    int v = (threadIdx.x < nch) ? g_bsum[threadIdx.x] : 0;
    sm[threadIdx.x] = v;
    __syncthreads();
    for (int off = 1; off < 128; off <<= 1) {
        int t = (threadIdx.x >= off) ? sm[threadIdx.x - off] : 0;
        __syncthreads();
        sm[threadIdx.x] += t;
        __syncthreads();
    }
    if (threadIdx.x < nch) g_bofs[threadIdx.x] = sm[threadIdx.x] - v;
}
__global__ void scan3() {
    int i = blockIdx.x * blockDim.x + threadIdx.x;
    if (i < NN) {
        int off = g_incl[i] - g_cnt[i] + g_bofs[i >> 9];
        g_rowoff[i] = off;
        g_cursor[i] = off;
    }
    if (i == 0) g_rowoff[NN] = EE;
}
__global__ void scatter(const int* __restrict__ src, const int* __restrict__ dst) {
    int e = blockIdx.x * blockDim.x + threadIdx.x;
    if (e < EE) {
        int d = dst[e];
        int pos = atomicAdd(&g_cursor[d], 1);
        g_csr[pos] = src[e];
    }
}

// ---------------- fp32 GEMM: C[nrows,KOUT] = A[nrows,128] @ W[128,KOUT] -----
// block = 256 threads (8 warps), warp = 4 rows x 64 cols, blockIdx.y = col tile
template <int KOUT, bool RELU>
__global__ void __launch_bounds__(256) gemm_kernel(
    const float* __restrict__ A, const float* __restrict__ W,
    const float* __restrict__ bias, float* __restrict__ C, int nrows) {
    __shared__ float Wsm[128 * 64];
    int colbase = blockIdx.y * 64;
    for (int i = threadIdx.x; i < 128 * 64; i += blockDim.x) {
        int k = i >> 6, c = i & 63;
        Wsm[i] = W[k * KOUT + colbase + c];
    }
    __syncthreads();
    int warp = threadIdx.x >> 5, lane = threadIdx.x & 31;
    int row0 = (blockIdx.x * 8 + warp) * 4;
    if (row0 >= nrows) return;
    float acc[4][2] = {};
    int c0 = lane * 2;
    for (int k = 0; k < 128; k += 4) {
        float4 a[4];
#pragma unroll
        for (int r = 0; r < 4; r++) {
            int row = row0 + r;
            if (row >= nrows) row = nrows - 1;
            a[r] = *reinterpret_cast<const float4*>(&A[(size_t)row * 128 + k]);
        }
#pragma unroll
        for (int kk = 0; kk < 4; kk++) {
            float2 wv = *reinterpret_cast<const float2*>(&Wsm[(k + kk) * 64 + c0]);
#pragma unroll
            for (int r = 0; r < 4; r++) {
                float av = (&a[r].x)[kk];
                acc[r][0] = fmaf(av, wv.x, acc[r][0]);
                acc[r][1] = fmaf(av, wv.y, acc[r][1]);
            }
        }
    }
    float b0 = 0.f, b1 = 0.f;
    if (bias) { b0 = bias[colbase + c0]; b1 = bias[colbase + c0 + 1]; }
#pragma unroll
    for (int r = 0; r < 4; r++) {
        int row = row0 + r;
        if (row < nrows) {
            float v0 = acc[r][0] + b0, v1 = acc[r][1] + b1;
            if (RELU) { v0 = fmaxf(v0, 0.f); v1 = fmaxf(v1, 0.f); }
            float2 o = make_float2(v0, v1);
            *reinterpret_cast<float2*>(&C[(size_t)row * KOUT + colbase + c0]) = o;
        }
    }
}

// ---------------- per-node attention logit scalars --------------------------
// alpha_s[n,h] = dot(hw[n, 16h:16h+16], a_src[h]); warp per node
__global__ void alpha_kernel(const float* __restrict__ a_src,
                             const float* __restrict__ a_dst) {
    int w = (blockIdx.x * blockDim.x + threadIdx.x) >> 5;
    int lane = threadIdx.x & 31;
    if (w >= NN) return;
    float4 v = *reinterpret_cast<const float4*>(&g_hw[(size_t)w * 128 + lane * 4]);
    float4 s4 = *reinterpret_cast<const float4*>(&a_src[lane * 4]);
    float4 d4 = *reinterpret_cast<const float4*>(&a_dst[lane * 4]);
    float ds = v.x * s4.x + v.y * s4.y + v.z * s4.z + v.w * s4.w;
    float dd = v.x * d4.x + v.y * d4.y + v.z * d4.z + v.w * d4.w;
    ds += __shfl_xor_sync(0xffffffffu, ds, 1);
    ds += __shfl_xor_sync(0xffffffffu, ds, 2);
    dd += __shfl_xor_sync(0xffffffffu, dd, 1);
    dd += __shfl_xor_sync(0xffffffffu, dd, 2);
    if ((lane & 3) == 0) {
        g_as[w * 8 + (lane >> 2)] = ds;
        g_ad[w * 8 + (lane >> 2)] = dd;
    }
}

__device__ __forceinline__ float lrelu(float t) { return t > 0.f ? t : 0.2f * t; }

// ---------------- warp-per-node softmax aggregate + bias+relu+res+LN -------
__global__ void __launch_bounds__(256) aggregate_kernel(
    const float* __restrict__ gb, const float* __restrict__ lng,
    const float* __restrict__ lnb) {
    int n = (blockIdx.x * blockDim.x + threadIdx.x) >> 5;
    if (n >= NN) return;
    int lane = threadIdx.x & 31;
    int beg = g_rowoff[n], end = g_rowoff[n + 1];

    float adl = (lane < 8) ? g_ad[n * 8 + lane] : 0.f;
    float asl = (lane < 8) ? g_as[n * 8 + lane] : 0.f;
    float adv[8], selfl[8];
#pragma unroll
    for (int hh = 0; hh < 8; hh++) {
        adv[hh] = __shfl_sync(0xffffffffu, adl, hh);
        float s = __shfl_sync(0xffffffffu, asl, hh);
        selfl[hh] = lrelu(s + adv[hh]);
    }
    // pass 1: max over edges (self loop always included)
    float m[8];
#pragma unroll
    for (int hh = 0; hh < 8; hh++) m[hh] = selfl[hh];
    for (int i = beg + lane; i < end; i += 32) {
        int s = g_csr[i];
#pragma unroll
        for (int hh = 0; hh < 8; hh++)
            m[hh] = fmaxf(m[hh], lrelu(g_as[s * 8 + hh] + adv[hh]));
    }
#pragma unroll
    for (int hh = 0; hh < 8; hh++)
#pragma unroll
        for (int off = 16; off; off >>= 1)
            m[hh] = fmaxf(m[hh], __shfl_xor_sync(0xffffffffu, m[hh], off));
    // pass 2: denominator
    float dsum[8];
#pragma unroll
    for (int hh = 0; hh < 8; hh++)
        dsum[hh] = (lane == 0) ? __expf(selfl[hh] - m[hh]) : 0.f;
    for (int i = beg + lane; i < end; i += 32) {
        int s = g_csr[i];
#pragma unroll
        for (int hh = 0; hh < 8; hh++)
            dsum[hh] += __expf(lrelu(g_as[s * 8 + hh] + adv[hh]) - m[hh]);
    }
#pragma unroll
    for (int hh = 0; hh < 8; hh++)
#pragma unroll
        for (int off = 16; off; off >>= 1)
            dsum[hh] += __shfl_xor_sync(0xffffffffu, dsum[hh], off);
    float invd[8];
#pragma unroll
    for (int hh = 0; hh < 8; hh++) invd[hh] = 1.0f / dsum[hh];

    // pass 3: weighted aggregation; lane owns dims [4*lane,4*lane+4), head = lane/4
    int c0 = lane * 4;
    int mh = lane >> 2;
    float mm = 0.f, iv = 0.f, sl = 0.f;
#pragma unroll
    for (int hh = 0; hh < 8; hh++)
        if (mh == hh) { mm = m[hh]; iv = invd[hh]; sl = selfl[hh]; }
    float admh = __shfl_sync(0xffffffffu, adl, mh);

    float a0, a1, a2, a3;
    {
        float wgt = __expf(sl - mm) * iv;  // self loop
        float4 v = *reinterpret_cast<const float4*>(&g_hw[(size_t)n * 128 + c0]);
        a0 = v.x * wgt; a1 = v.y * wgt; a2 = v.z * wgt; a3 = v.w * wgt;
    }
    for (int i = beg; i < end; i++) {
        int s = g_csr[i];
        float t = lrelu(g_as[s * 8 + mh] + admh);
        float wgt = __expf(t - mm) * iv;
        float4 v = *reinterpret_cast<const float4*>(&g_hw[(size_t)s * 128 + c0]);
        a0 = fmaf(v.x, wgt, a0);
        a1 = fmaf(v.y, wgt, a1);
        a2 = fmaf(v.z, wgt, a2);
        a3 = fmaf(v.w, wgt, a3);
    }
    // epilogue: + gat bias, relu, + residual, LayerNorm
    float4 b4 = *reinterpret_cast<const float4*>(&gb[c0]);
    float v0 = fmaxf(a0 + b4.x, 0.f), v1 = fmaxf(a1 + b4.y, 0.f);
    float v2 = fmaxf(a2 + b4.z, 0.f), v3 = fmaxf(a3 + b4.w, 0.f);
    float4 r4 = *reinterpret_cast<const float4*>(&g_h[(size_t)n * 128 + c0]);
    v0 += r4.x; v1 += r4.y; v2 += r4.z; v3 += r4.w;
    float s1 = v0 + v1 + v2 + v3;
    float s2 = v0 * v0 + v1 * v1 + v2 * v2 + v3 * v3;
#pragma unroll
    for (int off = 16; off; off >>= 1) {
        s1 += __shfl_xor_sync(0xffffffffu, s1, off);
        s2 += __shfl_xor_sync(0xffffffffu, s2, off);
    }
    float mu = s1 * (1.f / 128.f);
    float var = s2 * (1.f / 128.f) - mu * mu;
    float rstd = rsqrtf(fmaxf(var, 0.f) + 1e-5f);
    float4 g4 = *reinterpret_cast<const float4*>(&lng[c0]);
    float4 bb4 = *reinterpret_cast<const float4*>(&lnb[c0]);
    float4 o;
    o.x = (v0 - mu) * rstd * g4.x + bb4.x;
    o.y = (v1 - mu) * rstd * g4.y + bb4.y;
    o.z = (v2 - mu) * rstd * g4.z + bb4.z;
    o.w = (v3 - mu) * rstd * g4.w + bb4.w;
    *reinterpret_cast<float4*>(&g_h[(size_t)n * 128 + c0]) = o;
}

// ---------------- MLP head final: out = t2 @ W3 + b3 ------------------------
__global__ void head_kernel(const float* __restrict__ W3,
                            const float* __restrict__ b3,
                            float* __restrict__ out) {
    int w = (blockIdx.x * blockDim.x + threadIdx.x) >> 5;
    int lane = threadIdx.x & 31;
    if (w >= NN) return;
    float2 a = *reinterpret_cast<const float2*>(&g_h[(size_t)w * 64 + lane * 2]);
    float2 wv = *reinterpret_cast<const float2*>(&W3[lane * 2]);
    float s = a.x * wv.x + a.y * wv.y;
#pragma unroll
    for (int off = 16; off; off >>= 1) s += __shfl_xor_sync(0xffffffffu, s, off);
    if (lane == 0) out[w] = s + b3[0];
}

// ---------------- launch ----------------------------------------------------
extern "C" void kernel_launch(void* const* d_in, const int* in_sizes, int n_in,
                              void* d_out, int out_size) {
    const float* x = (const float*)d_in[0];
    const int* ei = (const int*)d_in[1];
    const int* src = ei;
    const int* dst = ei + EE;
    const float* W_in = (const float*)d_in[3];
    const float* b_in = (const float*)d_in[4];
    float* out = (float*)d_out;

    float *p_h = nullptr, *p_hw = nullptr;
    cudaGetSymbolAddress((void**)&p_h, g_h);
    cudaGetSymbolAddress((void**)&p_hw, g_hw);

    input_proj<<<(NN * HH + 255) / 256, 256>>>(x, W_in, b_in);

    zero_cnt<<<(NN + 255) / 256, 256>>>();
    count_kernel<<<(EE + 255) / 256, 256>>>(dst);
    scan1<<<(NN + 511) / 512, 512>>>();
    scan2<<<1, 128>>>((NN + 511) / 512);
    scan3<<<(NN + 255) / 256, 256>>>();
    scatter<<<(EE + 255) / 256, 256>>>(src, dst);

    int gx = (NN + 31) / 32;
    for (int l = 0; l < 3; l++) {
        const float* W  = (const float*)d_in[5 + 6 * l];
        const float* as = (const float*)d_in[6 + 6 * l];
        const float* ad = (const float*)d_in[7 + 6 * l];
        const float* gb = (const float*)d_in[8 + 6 * l];
        const float* lg = (const float*)d_in[9 + 6 * l];
        const float* lb = (const float*)d_in[10 + 6 * l];
        gemm_kernel<128, false><<<dim3(gx, 2), 256>>>(p_h, W, nullptr, p_hw, NN);
        alpha_kernel<<<(NN * 32 + 255) / 256, 256>>>(as, ad);
        aggregate_kernel<<<(NN + 7) / 8, 256>>>(gb, lg, lb);
    }
    // MLP head
    gemm_kernel<128, true><<<dim3(gx, 2), 256>>>(p_h, (const float*)d_in[23],
                                                 (const float*)d_in[24], p_hw, NN);
    gemm_kernel<64, true><<<dim3(gx, 1), 256>>>(p_hw, (const float*)d_in[25],
                                                (const float*)d_in[26], p_h, NN);
    head_kernel<<<(NN * 32 + 255) / 256, 256>>>((const float*)d_in[27],
                                                (const float*)d_in[28], out);
}

// round 3
// speedup vs baseline: 1.5177x; 1.5177x over previous
#include <cuda_runtime.h>
#include <math.h>
#include <stdint.h>

#define NN 50000
#define EE 600000
#define HH 128

// ---------------- static device scratch (no allocs allowed) ----------------
__device__ float g_h[NN * HH];      // current node features
__device__ float g_hw[NN * HH];     // h @ W
__device__ float g_as[NN * 8];      // alpha_src per node/head
__device__ float g_ad[NN * 8];      // alpha_dst per node/head
__device__ int   g_cnt[NN];
__device__ int   g_incl[NN];
__device__ int   g_rowoff[NN + 1];
__device__ int   g_cursor[NN];
__device__ int   g_bsum[128];
__device__ int   g_bofs[128];
__device__ int   g_csr[EE];

// ---------------- tf32 helpers ----------------------------------------------
__device__ __forceinline__ uint32_t f2tf32(float v) {
    uint32_t t;
    asm("cvt.rna.tf32.f32 %0, %1;" : "=r"(t) : "f"(v));
    return t;
}
__device__ __forceinline__ void mma_tf32(float& c0, float& c1, float& c2, float& c3,
                                         uint32_t a0, uint32_t a1, uint32_t a2, uint32_t a3,
                                         uint32_t b0, uint32_t b1) {
    asm volatile(
        "mma.sync.aligned.m16n8k8.row.col.f32.tf32.tf32.f32 "
        "{%0,%1,%2,%3}, {%4,%5,%6,%7}, {%8,%9}, {%0,%1,%2,%3};"
        : "+f"(c0), "+f"(c1), "+f"(c2), "+f"(c3)
        : "r"(a0), "r"(a1), "r"(a2), "r"(a3), "r"(b0), "r"(b1));
}

// ---------------- HMMA tf32 GEMM: C[rows,NCOLS] = A[rows,128] @ W[128,NCOLS]
// CTA tile 128 x NCOLS, 8 warps: 4 (m) x 2 (n). Warp tile 32 x NCOLS/2.
// SMEM holds A and W in fragment-major layout (conflict-free vector lds).
// MODE 0: plain store; MODE 1: bias + relu.
template <int NCOLS, int MODE>
__global__ void __launch_bounds__(256) mma_gemm(
    const float* __restrict__ A, const float* __restrict__ W,
    const float* __restrict__ bias, float* __restrict__ C, int nrows) {
    extern __shared__ float sm[];
    float* As = sm;              // [8 mtile][16 kstep][128]  = 16384 floats
    float* Bs = sm + 16384;      // [NCOLS/8 ntile][16 kstep][64]
    const int NT = NCOLS / 16;   // n-tiles per warp
    int tid = threadIdx.x;
    int row0 = blockIdx.x * 128;

    // stage A -> fragment-major (tf32-rounded)
    for (int i = tid; i < 128 * 128; i += 256) {
        int r = i >> 7, c = i & 127;
        int gr = row0 + r; if (gr >= nrows) gr = nrows - 1;
        uint32_t tv = f2tf32(A[(size_t)gr * 128 + c]);
        int mt = r >> 4, rr = r & 15, ks = c >> 3;
        int ln = ((rr & 7) << 2) | (c & 3);
        int rg = (rr >> 3) | (((c >> 2) & 1) << 1);
        As[((mt * 16 + ks) << 7) + (ln << 2) + rg] = __uint_as_float(tv);
    }
    // stage W -> fragment-major (B of mma is [k=8][n=8] "col")
    for (int i = tid; i < 128 * NCOLS; i += 256) {
        int k = i / NCOLS, n = i % NCOLS;
        uint32_t tv = f2tf32(W[i]);
        int nt = n >> 3, nn = n & 7, ks = k >> 3;
        int ln = (nn << 2) | (k & 3);
        int rg = (k >> 2) & 1;
        Bs[((nt * 16 + ks) << 6) + (ln << 1) + rg] = __uint_as_float(tv);
    }
    __syncthreads();

    int w = tid >> 5, lane = tid & 31;
    int wm = w >> 1, wn = w & 1;
    float acc[2][NT][4];
#pragma unroll
    for (int mi = 0; mi < 2; mi++)
#pragma unroll
        for (int ni = 0; ni < NT; ni++)
#pragma unroll
            for (int j = 0; j < 4; j++) acc[mi][ni][j] = 0.f;

#pragma unroll
    for (int ks = 0; ks < 16; ks++) {
        uint32_t af[2][4];
#pragma unroll
        for (int mi = 0; mi < 2; mi++) {
            const float4* p = reinterpret_cast<const float4*>(
                &As[(((wm * 2 + mi) * 16 + ks) << 7) + (lane << 2)]);
            float4 v = *p;
            af[mi][0] = __float_as_uint(v.x); af[mi][1] = __float_as_uint(v.y);
            af[mi][2] = __float_as_uint(v.z); af[mi][3] = __float_as_uint(v.w);
        }
        uint32_t bf[NT][2];
#pragma unroll
        for (int ni = 0; ni < NT; ni++) {
            const float2* p = reinterpret_cast<const float2*>(
                &Bs[(((wn * NT + ni) * 16 + ks) << 6) + (lane << 1)]);
            float2 v = *p;
            bf[ni][0] = __float_as_uint(v.x); bf[ni][1] = __float_as_uint(v.y);
        }
#pragma unroll
        for (int mi = 0; mi < 2; mi++)
#pragma unroll
            for (int ni = 0; ni < NT; ni++)
                mma_tf32(acc[mi][ni][0], acc[mi][ni][1], acc[mi][ni][2], acc[mi][ni][3],
                         af[mi][0], af[mi][1], af[mi][2], af[mi][3],
                         bf[ni][0], bf[ni][1]);
    }

    // epilogue
    int grp = lane >> 2, qd = lane & 3;
#pragma unroll
    for (int mi = 0; mi < 2; mi++) {
#pragma unroll
        for (int ni = 0; ni < NT; ni++) {
            int r = row0 + wm * 32 + mi * 16 + grp;
            int cb = wn * (NCOLS / 2) + ni * 8 + (qd << 1);
            float v0 = acc[mi][ni][0], v1 = acc[mi][ni][1];
            float v2 = acc[mi][ni][2], v3 = acc[mi][ni][3];
            if (MODE == 1) {
                float b0 = bias[cb], b1 = bias[cb + 1];
                v0 = fmaxf(v0 + b0, 0.f); v1 = fmaxf(v1 + b1, 0.f);
                v2 = fmaxf(v2 + b0, 0.f); v3 = fmaxf(v3 + b1, 0.f);
            }
            if (r < nrows)
                *reinterpret_cast<float2*>(&C[(size_t)r * NCOLS + cb]) = make_float2(v0, v1);
            if (r + 8 < nrows)
                *reinterpret_cast<float2*>(&C[(size_t)(r + 8) * NCOLS + cb]) = make_float2(v2, v3);
        }
    }
}

// ---------------- input projection: h = x @ W_in + b_in --------------------
__global__ void input_proj(const float* __restrict__ x,
                           const float* __restrict__ W_in,
                           const float* __restrict__ b_in) {
    int idx = blockIdx.x * blockDim.x + threadIdx.x;
    if (idx >= NN * HH) return;
    int n = idx >> 7, j = idx & 127;
    g_h[idx] = x[n * 2] * W_in[j] + x[n * 2 + 1] * W_in[128 + j] + b_in[j];
}

// ---------------- CSR build -------------------------------------------------
__global__ void zero_cnt() {
    int i = blockIdx.x * blockDim.x + threadIdx.x;
    if (i < NN) g_cnt[i] = 0;
}
__global__ void count_kernel(const int* __restrict__ dst) {
    int e = blockIdx.x * blockDim.x + threadIdx.x;
    if (e < EE) atomicAdd(&g_cnt[dst[e]], 1);
}
__global__ void scan1() {
    __shared__ int sm[512];
    int i = blockIdx.x * 512 + threadIdx.x;
    int v = (i < NN) ? g_cnt[i] : 0;
    sm[threadIdx.x] = v;
    __syncthreads();
    for (int off = 1; off < 512; off <<= 1) {
        int t = (threadIdx.x >= off) ? sm[threadIdx.x - off] : 0;
        __syncthreads();
        sm[threadIdx.x] += t;
        __syncthreads();
    }
    if (i < NN) g_incl[i] = sm[threadIdx.x];
    if (threadIdx.x == 511) g_bsum[blockIdx.x] = sm[511];
}
__global__ void scan2(int nch) {
    __shared__ int sm[128];
    int v = (threadIdx.x < nch) ? g_bsum[threadIdx.x] : 0;
    sm[threadIdx.x] = v;
    __syncthreads();
    for (int off = 1; off < 128; off <<= 1) {
        int t = (threadIdx.x >= off) ? sm[threadIdx.x - off] : 0;
        __syncthreads();
        sm[threadIdx.x] += t;
        __syncthreads();
    }
    if (threadIdx.x < nch) g_bofs[threadIdx.x] = sm[threadIdx.x] - v;
}
__global__ void scan3() {
    int i = blockIdx.x * blockDim.x + threadIdx.x;
    if (i < NN) {
        int off = g_incl[i] - g_cnt[i] + g_bofs[i >> 9];
        g_rowoff[i] = off;
        g_cursor[i] = off;
    }
    if (i == 0) g_rowoff[NN] = EE;
}
__global__ void scatter(const int* __restrict__ src, const int* __restrict__ dst) {
    int e = blockIdx.x * blockDim.x + threadIdx.x;
    if (e < EE) {
        int d = dst[e];
        int pos = atomicAdd(&g_cursor[d], 1);
        g_csr[pos] = src[e];
    }
}

// ---------------- per-node attention logit scalars --------------------------
__global__ void alpha_kernel(const float* __restrict__ a_src,
                             const float* __restrict__ a_dst) {
    int w = (blockIdx.x * blockDim.x + threadIdx.x) >> 5;
    int lane = threadIdx.x & 31;
    if (w >= NN) return;
    float4 v = *reinterpret_cast<const float4*>(&g_hw[(size_t)w * 128 + lane * 4]);
    float4 s4 = *reinterpret_cast<const float4*>(&a_src[lane * 4]);
    float4 d4 = *reinterpret_cast<const float4*>(&a_dst[lane * 4]);
    float ds = v.x * s4.x + v.y * s4.y + v.z * s4.z + v.w * s4.w;
    float dd = v.x * d4.x + v.y * d4.y + v.z * d4.z + v.w * d4.w;
    ds += __shfl_xor_sync(0xffffffffu, ds, 1);
    ds += __shfl_xor_sync(0xffffffffu, ds, 2);
    dd += __shfl_xor_sync(0xffffffffu, dd, 1);
    dd += __shfl_xor_sync(0xffffffffu, dd, 2);
    if ((lane & 3) == 0) {
        g_as[w * 8 + (lane >> 2)] = ds;
        g_ad[w * 8 + (lane >> 2)] = dd;
    }
}

__device__ __forceinline__ float lrelu(float t) { return t > 0.f ? t : 0.2f * t; }

// ---------------- warp-per-node softmax aggregate + bias+relu+res+LN -------
__global__ void __launch_bounds__(256) aggregate_kernel(
    const float* __restrict__ gb, const float* __restrict__ lng,
    const float* __restrict__ lnb) {
    int n = (blockIdx.x * blockDim.x + threadIdx.x) >> 5;
    if (n >= NN) return;
    int lane = threadIdx.x & 31;
    int beg = g_rowoff[n], end = g_rowoff[n + 1];

    float adl = (lane < 8) ? g_ad[n * 8 + lane] : 0.f;
    float asl = (lane < 8) ? g_as[n * 8 + lane] : 0.f;
    float adv[8], selfl[8];
#pragma unroll
    for (int hh = 0; hh < 8; hh++) {
        adv[hh] = __shfl_sync(0xffffffffu, adl, hh);
        float s = __shfl_sync(0xffffffffu, asl, hh);
        selfl[hh] = lrelu(s + adv[hh]);
    }
    float m[8];
#pragma unroll
    for (int hh = 0; hh < 8; hh++) m[hh] = selfl[hh];
    for (int i = beg + lane; i < end; i += 32) {
        int s = g_csr[i];
#pragma unroll
        for (int hh = 0; hh < 8; hh++)
            m[hh] = fmaxf(m[hh], lrelu(g_as[s * 8 + hh] + adv[hh]));
    }
#pragma unroll
    for (int hh = 0; hh < 8; hh++)
#pragma unroll
        for (int off = 16; off; off >>= 1)
            m[hh] = fmaxf(m[hh], __shfl_xor_sync(0xffffffffu, m[hh], off));
    float dsum[8];
#pragma unroll
    for (int hh = 0; hh < 8; hh++)
        dsum[hh] = (lane == 0) ? __expf(selfl[hh] - m[hh]) : 0.f;
    for (int i = beg + lane; i < end; i += 32) {
        int s = g_csr[i];
#pragma unroll
        for (int hh = 0; hh < 8; hh++)
            dsum[hh] += __expf(lrelu(g_as[s * 8 + hh] + adv[hh]) - m[hh]);
    }
#pragma unroll
    for (int hh = 0; hh < 8; hh++)
#pragma unroll
        for (int off = 16; off; off >>= 1)
            dsum[hh] += __shfl_xor_sync(0xffffffffu, dsum[hh], off);
    float invd[8];
#pragma unroll
    for (int hh = 0; hh < 8; hh++) invd[hh] = 1.0f / dsum[hh];

    int c0 = lane * 4;
    int mh = lane >> 2;
    float mm = 0.f, iv = 0.f, sl = 0.f;
#pragma unroll
    for (int hh = 0; hh < 8; hh++)
        if (mh == hh) { mm = m[hh]; iv = invd[hh]; sl = selfl[hh]; }
    float admh = __shfl_sync(0xffffffffu, adl, mh);

    float a0, a1, a2, a3;
    {
        float wgt = __expf(sl - mm) * iv;
        float4 v = *reinterpret_cast<const float4*>(&g_hw[(size_t)n * 128 + c0]);
        a0 = v.x * wgt; a1 = v.y * wgt; a2 = v.z * wgt; a3 = v.w * wgt;
    }
    for (int i = beg; i < end; i++) {
        int s = g_csr[i];
        float t = lrelu(g_as[s * 8 + mh] + admh);
        float wgt = __expf(t - mm) * iv;
        float4 v = *reinterpret_cast<const float4*>(&g_hw[(size_t)s * 128 + c0]);
        a0 = fmaf(v.x, wgt, a0);
        a1 = fmaf(v.y, wgt, a1);
        a2 = fmaf(v.z, wgt, a2);
        a3 = fmaf(v.w, wgt, a3);
    }
    float4 b4 = *reinterpret_cast<const float4*>(&gb[c0]);
    float v0 = fmaxf(a0 + b4.x, 0.f), v1 = fmaxf(a1 + b4.y, 0.f);
    float v2 = fmaxf(a2 + b4.z, 0.f), v3 = fmaxf(a3 + b4.w, 0.f);
    float4 r4 = *reinterpret_cast<const float4*>(&g_h[(size_t)n * 128 + c0]);
    v0 += r4.x; v1 += r4.y; v2 += r4.z; v3 += r4.w;
    float s1 = v0 + v1 + v2 + v3;
    float s2 = v0 * v0 + v1 * v1 + v2 * v2 + v3 * v3;
#pragma unroll
    for (int off = 16; off; off >>= 1) {
        s1 += __shfl_xor_sync(0xffffffffu, s1, off);
        s2 += __shfl_xor_sync(0xffffffffu, s2, off);
    }
    float mu = s1 * (1.f / 128.f);
    float var = s2 * (1.f / 128.f) - mu * mu;
    float rstd = rsqrtf(fmaxf(var, 0.f) + 1e-5f);
    float4 g4 = *reinterpret_cast<const float4*>(&lng[c0]);
    float4 bb4 = *reinterpret_cast<const float4*>(&lnb[c0]);
    float4 o;
    o.x = (v0 - mu) * rstd * g4.x + bb4.x;
    o.y = (v1 - mu) * rstd * g4.y + bb4.y;
    o.z = (v2 - mu) * rstd * g4.z + bb4.z;
    o.w = (v3 - mu) * rstd * g4.w + bb4.w;
    *reinterpret_cast<float4*>(&g_h[(size_t)n * 128 + c0]) = o;
}

// ---------------- MLP head final: out = t2 @ W3 + b3 ------------------------
__global__ void head_kernel(const float* __restrict__ W3,
                            const float* __restrict__ b3,
                            float* __restrict__ out) {
    int w = (blockIdx.x * blockDim.x + threadIdx.x) >> 5;
    int lane = threadIdx.x & 31;
    if (w >= NN) return;
    float2 a = *reinterpret_cast<const float2*>(&g_h[(size_t)w * 64 + lane * 2]);
    float2 wv = *reinterpret_cast<const float2*>(&W3[lane * 2]);
    float s = a.x * wv.x + a.y * wv.y;
#pragma unroll
    for (int off = 16; off; off >>= 1) s += __shfl_xor_sync(0xffffffffu, s, off);
    if (lane == 0) out[w] = s + b3[0];
}

// ---------------- launch ----------------------------------------------------
extern "C" void kernel_launch(void* const* d_in, const int* in_sizes, int n_in,
                              void* d_out, int out_size) {
    const float* x = (const float*)d_in[0];
    const int* ei = (const int*)d_in[1];
    const int* src = ei;
    const int* dst = ei + EE;
    const float* W_in = (const float*)d_in[3];
    const float* b_in = (const float*)d_in[4];
    float* out = (float*)d_out;

    float *p_h = nullptr, *p_hw = nullptr;
    cudaGetSymbolAddress((void**)&p_h, g_h);
    cudaGetSymbolAddress((void**)&p_hw, g_hw);

    const int SMEM_128 = (16384 + 16384) * 4;   // 128 KB
    const int SMEM_64  = (16384 + 8192) * 4;    // 96 KB
    cudaFuncSetAttribute(mma_gemm<128, 0>, cudaFuncAttributeMaxDynamicSharedMemorySize, SMEM_128);
    cudaFuncSetAttribute(mma_gemm<128, 1>, cudaFuncAttributeMaxDynamicSharedMemorySize, SMEM_128);
    cudaFuncSetAttribute(mma_gemm<64, 1>,  cudaFuncAttributeMaxDynamicSharedMemorySize, SMEM_64);
    const int NCTA = (NN + 127) / 128;  // 391

    input_proj<<<(NN * HH + 255) / 256, 256>>>(x, W_in, b_in);

    zero_cnt<<<(NN + 255) / 256, 256>>>();
    count_kernel<<<(EE + 255) / 256, 256>>>(dst);
    scan1<<<(NN + 511) / 512, 512>>>();
    scan2<<<1, 128>>>((NN + 511) / 512);
    scan3<<<(NN + 255) / 256, 256>>>();
    scatter<<<(EE + 255) / 256, 256>>>(src, dst);

    for (int l = 0; l < 3; l++) {
        const float* W  = (const float*)d_in[5 + 6 * l];
        const float* as = (const float*)d_in[6 + 6 * l];
        const float* ad = (const float*)d_in[7 + 6 * l];
        const float* gb = (const float*)d_in[8 + 6 * l];
        const float* lg = (const float*)d_in[9 + 6 * l];
        const float* lb = (const float*)d_in[10 + 6 * l];
        mma_gemm<128, 0><<<NCTA, 256, SMEM_128>>>(p_h, W, nullptr, p_hw, NN);
        alpha_kernel<<<(NN * 32 + 255) / 256, 256>>>(as, ad);
        aggregate_kernel<<<(NN + 7) / 8, 256>>>(gb, lg, lb);
    }
    // MLP head
    mma_gemm<128, 1><<<NCTA, 256, SMEM_128>>>(p_h, (const float*)d_in[23],
                                              (const float*)d_in[24], p_hw, NN);
    mma_gemm<64, 1><<<NCTA, 256, SMEM_64>>>(p_hw, (const float*)d_in[25],
                                            (const float*)d_in[26], p_h, NN);
    head_kernel<<<(NN * 32 + 255) / 256, 256>>>((const float*)d_in[27],
                                                (const float*)d_in[28], out);
}

// round 4
// speedup vs baseline: 1.7587x; 1.1588x over previous
#include <cuda_runtime.h>
#include <math.h>
#include <stdint.h>

#define NN 50000
#define EE 600000
#define HH 128

// ---------------- static device scratch (no allocs allowed) ----------------
__device__ float g_h[NN * HH];      // current node features
__device__ float g_hw[NN * HH];     // h @ W
__device__ float g_as[NN * 8];      // alpha_src per node/head
__device__ float g_ad[NN * 8];      // alpha_dst per node/head
__device__ int   g_cnt[NN];
__device__ int   g_incl[NN];
__device__ int   g_rowoff[NN + 1];
__device__ int   g_cursor[NN];
__device__ int   g_bsum[128];
__device__ int   g_bofs[128];
__device__ int   g_csr[EE];

// ---------------- tf32 helpers ----------------------------------------------
__device__ __forceinline__ uint32_t f2tf32(float v) {
    uint32_t t;
    asm("cvt.rna.tf32.f32 %0, %1;" : "=r"(t) : "f"(v));
    return t;
}
__device__ __forceinline__ void mma_tf32(float& c0, float& c1, float& c2, float& c3,
                                         uint32_t a0, uint32_t a1, uint32_t a2, uint32_t a3,
                                         uint32_t b0, uint32_t b1) {
    asm volatile(
        "mma.sync.aligned.m16n8k8.row.col.f32.tf32.tf32.f32 "
        "{%0,%1,%2,%3}, {%4,%5,%6,%7}, {%8,%9}, {%0,%1,%2,%3};"
        : "+f"(c0), "+f"(c1), "+f"(c2), "+f"(c3)
        : "r"(a0), "r"(a1), "r"(a2), "r"(a3), "r"(b0), "r"(b1));
}

// ---------------- HMMA tf32 GEMM: C[rows, ncols] = A[rows,128] @ W[128,ncols]
// CTA tile: 128 rows x 64 cols (col tile chosen by blockIdx.y).
// 8 warps: 4 (m) x 2 (n); warp tile 32 rows x 32 cols (NT=4 n-tiles of 8).
// SMEM: A 64KB + B 32KB = 96KB -> 2 CTAs/SM.
// MODE 0: store C + fused per-head attention dots (aux0=a_src, aux1=a_dst)
// MODE 1: bias (aux0) + relu
template <int MODE>
__global__ void __launch_bounds__(256) mma_gemm(
    const float* __restrict__ A, const float* __restrict__ W, int ncols,
    const float* __restrict__ aux0, const float* __restrict__ aux1,
    float* __restrict__ C, int nrows) {
    extern __shared__ float sm[];
    float* As = sm;              // [8 mtile][16 kstep][128] = 16384 floats
    float* Bs = sm + 16384;      // [8 ntile][16 kstep][64]  = 8192 floats
    int tid = threadIdx.x;
    int row0 = blockIdx.x * 128;
    int colbase = blockIdx.y * 64;

    // stage A -> fragment-major (tf32-rounded), lda = 128 always
    for (int i = tid; i < 128 * 128; i += 256) {
        int r = i >> 7, c = i & 127;
        int gr = row0 + r; if (gr >= nrows) gr = nrows - 1;
        uint32_t tv = f2tf32(A[(size_t)gr * 128 + c]);
        int mt = r >> 4, rr = r & 15, ks = c >> 3;
        int ln = ((rr & 7) << 2) | (c & 3);
        int rg = (rr >> 3) | (((c >> 2) & 1) << 1);
        As[((mt * 16 + ks) << 7) + (ln << 2) + rg] = __uint_as_float(tv);
    }
    // stage W cols [colbase, colbase+64) -> fragment-major
    for (int i = tid; i < 128 * 64; i += 256) {
        int k = i >> 6, n = i & 63;
        uint32_t tv = f2tf32(W[(size_t)k * ncols + colbase + n]);
        int nt = n >> 3, nn = n & 7, ks = k >> 3;
        int ln = (nn << 2) | (k & 3);
        int rg = (k >> 2) & 1;
        Bs[((nt * 16 + ks) << 6) + (ln << 1) + rg] = __uint_as_float(tv);
    }
    __syncthreads();

    int w = tid >> 5, lane = tid & 31;
    int wm = w >> 1, wn = w & 1;
    float acc[2][4][4];
#pragma unroll
    for (int mi = 0; mi < 2; mi++)
#pragma unroll
        for (int ni = 0; ni < 4; ni++)
#pragma unroll
            for (int j = 0; j < 4; j++) acc[mi][ni][j] = 0.f;

#pragma unroll
    for (int ks = 0; ks < 16; ks++) {
        uint32_t af[2][4];
#pragma unroll
        for (int mi = 0; mi < 2; mi++) {
            float4 v = *reinterpret_cast<const float4*>(
                &As[(((wm * 2 + mi) * 16 + ks) << 7) + (lane << 2)]);
            af[mi][0] = __float_as_uint(v.x); af[mi][1] = __float_as_uint(v.y);
            af[mi][2] = __float_as_uint(v.z); af[mi][3] = __float_as_uint(v.w);
        }
        uint32_t bf[4][2];
#pragma unroll
        for (int ni = 0; ni < 4; ni++) {
            float2 v = *reinterpret_cast<const float2*>(
                &Bs[(((wn * 4 + ni) * 16 + ks) << 6) + (lane << 1)]);
            bf[ni][0] = __float_as_uint(v.x); bf[ni][1] = __float_as_uint(v.y);
        }
#pragma unroll
        for (int mi = 0; mi < 2; mi++)
#pragma unroll
            for (int ni = 0; ni < 4; ni++)
                mma_tf32(acc[mi][ni][0], acc[mi][ni][1], acc[mi][ni][2], acc[mi][ni][3],
                         af[mi][0], af[mi][1], af[mi][2], af[mi][3],
                         bf[ni][0], bf[ni][1]);
    }

    int grp = lane >> 2, qd = lane & 3;

    // fused attention dots (MODE 0): warp covers 32 cols = 2 complete heads
    float asr[2][2][2], adr[2][2][2];  // [mi][rowhalf][headpair]
    if (MODE == 0) {
#pragma unroll
        for (int mi = 0; mi < 2; mi++)
#pragma unroll
            for (int rh = 0; rh < 2; rh++)
#pragma unroll
                for (int hp = 0; hp < 2; hp++) { asr[mi][rh][hp] = 0.f; adr[mi][rh][hp] = 0.f; }
    }

#pragma unroll
    for (int mi = 0; mi < 2; mi++) {
#pragma unroll
        for (int ni = 0; ni < 4; ni++) {
            int cb = colbase + wn * 32 + ni * 8 + (qd << 1);
            int r = row0 + wm * 32 + mi * 16 + grp;
            float v0 = acc[mi][ni][0], v1 = acc[mi][ni][1];
            float v2 = acc[mi][ni][2], v3 = acc[mi][ni][3];
            if (MODE == 1) {
                float b0 = aux0[cb], b1 = aux0[cb + 1];
                v0 = fmaxf(v0 + b0, 0.f); v1 = fmaxf(v1 + b1, 0.f);
                v2 = fmaxf(v2 + b0, 0.f); v3 = fmaxf(v3 + b1, 0.f);
            }
            if (MODE == 0) {
                int hp = ni >> 1;
                float a0 = aux0[cb], a1 = aux0[cb + 1];
                float d0 = aux1[cb], d1 = aux1[cb + 1];
                asr[mi][0][hp] += v0 * a0 + v1 * a1;
                asr[mi][1][hp] += v2 * a0 + v3 * a1;
                adr[mi][0][hp] += v0 * d0 + v1 * d1;
                adr[mi][1][hp] += v2 * d0 + v3 * d1;
            }
            if (r < nrows)
                *reinterpret_cast<float2*>(&C[(size_t)r * ncols + cb]) = make_float2(v0, v1);
            if (r + 8 < nrows)
                *reinterpret_cast<float2*>(&C[(size_t)(r + 8) * ncols + cb]) = make_float2(v2, v3);
        }
    }

    if (MODE == 0) {
        // reduce over the 4 quad lanes (same grp)
#pragma unroll
        for (int mi = 0; mi < 2; mi++)
#pragma unroll
            for (int rh = 0; rh < 2; rh++)
#pragma unroll
                for (int hp = 0; hp < 2; hp++) {
                    float a = asr[mi][rh][hp], d = adr[mi][rh][hp];
                    a += __shfl_xor_sync(0xffffffffu, a, 1);
                    a += __shfl_xor_sync(0xffffffffu, a, 2);
                    d += __shfl_xor_sync(0xffffffffu, d, 1);
                    d += __shfl_xor_sync(0xffffffffu, d, 2);
                    asr[mi][rh][hp] = a; adr[mi][rh][hp] = d;
                }
        if (qd == 0) {
            int h0 = (colbase + wn * 32) >> 4;
#pragma unroll
            for (int mi = 0; mi < 2; mi++)
#pragma unroll
                for (int rh = 0; rh < 2; rh++) {
                    int r = row0 + wm * 32 + mi * 16 + grp + rh * 8;
                    if (r < nrows) {
#pragma unroll
                        for (int hp = 0; hp < 2; hp++) {
                            g_as[r * 8 + h0 + hp] = asr[mi][rh][hp];
                            g_ad[r * 8 + h0 + hp] = adr[mi][rh][hp];
                        }
                    }
                }
        }
    }
}

// ---------------- input projection: h = x @ W_in + b_in --------------------
__global__ void input_proj(const float* __restrict__ x,
                           const float* __restrict__ W_in,
                           const float* __restrict__ b_in) {
    int idx = blockIdx.x * blockDim.x + threadIdx.x;
    if (idx >= NN * HH) return;
    int n = idx >> 7, j = idx & 127;
    g_h[idx] = x[n * 2] * W_in[j] + x[n * 2 + 1] * W_in[128 + j] + b_in[j];
}

// ---------------- CSR build -------------------------------------------------
__global__ void count_kernel(const int* __restrict__ dst) {
    int e = blockIdx.x * blockDim.x + threadIdx.x;
    if (e < EE) atomicAdd(&g_cnt[dst[e]], 1);
}
__global__ void scan1() {
    __shared__ int sm[512];
    int i = blockIdx.x * 512 + threadIdx.x;
    int v = (i < NN) ? g_cnt[i] : 0;
    sm[threadIdx.x] = v;
    __syncthreads();
    for (int off = 1; off < 512; off <<= 1) {
        int t = (threadIdx.x >= off) ? sm[threadIdx.x - off] : 0;
        __syncthreads();
        sm[threadIdx.x] += t;
        __syncthreads();
    }
    if (i < NN) g_incl[i] = sm[threadIdx.x];
    if (threadIdx.x == 511) g_bsum[blockIdx.x] = sm[511];
}
__global__ void scan2(int nch) {
    __shared__ int sm[128];
    int v = (threadIdx.x < nch) ? g_bsum[threadIdx.x] : 0;
    sm[threadIdx.x] = v;
    __syncthreads();
    for (int off = 1; off < 128; off <<= 1) {
        int t = (threadIdx.x >= off) ? sm[threadIdx.x - off] : 0;
        __syncthreads();
        sm[threadIdx.x] += t;
        __syncthreads();
    }
    if (threadIdx.x < nch) g_bofs[threadIdx.x] = sm[threadIdx.x] - v;
}
__global__ void scan3() {
    int i = blockIdx.x * blockDim.x + threadIdx.x;
    if (i < NN) {
        int off = g_incl[i] - g_cnt[i] + g_bofs[i >> 9];
        g_rowoff[i] = off;
        g_cursor[i] = off;
    }
    if (i == 0) g_rowoff[NN] = EE;
}
__global__ void scatter(const int* __restrict__ src, const int* __restrict__ dst) {
    int e = blockIdx.x * blockDim.x + threadIdx.x;
    if (e < EE) {
        int d = dst[e];
        int pos = atomicAdd(&g_cursor[d], 1);
        g_csr[pos] = src[e];
    }
}

__device__ __forceinline__ float lrelu(float t) { return t > 0.f ? t : 0.2f * t; }

// ---------------- warp-per-node softmax aggregate + bias+relu+res+LN -------
// 2 passes (no max-pass: logits are O(1), exp is safe)
__global__ void __launch_bounds__(256) aggregate_kernel(
    const float* __restrict__ gb, const float* __restrict__ lng,
    const float* __restrict__ lnb) {
    int n = (blockIdx.x * blockDim.x + threadIdx.x) >> 5;
    if (n >= NN) return;
    int lane = threadIdx.x & 31;
    int beg = g_rowoff[n], end = g_rowoff[n + 1];

    float adl = (lane < 8) ? g_ad[n * 8 + lane] : 0.f;
    float asl = (lane < 8) ? g_as[n * 8 + lane] : 0.f;
    float adv[8], selfl[8];
#pragma unroll
    for (int hh = 0; hh < 8; hh++) {
        adv[hh] = __shfl_sync(0xffffffffu, adl, hh);
        float s = __shfl_sync(0xffffffffu, asl, hh);
        selfl[hh] = lrelu(s + adv[hh]);
    }
    // pass 1: denominator (self loop included on lane 0)
    float dsum[8];
#pragma unroll
    for (int hh = 0; hh < 8; hh++)
        dsum[hh] = (lane == 0) ? __expf(selfl[hh]) : 0.f;
    for (int i = beg + lane; i < end; i += 32) {
        int s = g_csr[i];
#pragma unroll
        for (int hh = 0; hh < 8; hh++)
            dsum[hh] += __expf(lrelu(g_as[s * 8 + hh] + adv[hh]));
    }
#pragma unroll
    for (int hh = 0; hh < 8; hh++)
#pragma unroll
        for (int off = 16; off; off >>= 1)
            dsum[hh] += __shfl_xor_sync(0xffffffffu, dsum[hh], off);
    float invd[8];
#pragma unroll
    for (int hh = 0; hh < 8; hh++) invd[hh] = 1.0f / dsum[hh];

    // pass 2: weighted aggregation; lane owns dims [4*lane,4*lane+4), head = lane/4
    int c0 = lane * 4;
    int mh = lane >> 2;
    float iv = 0.f, sl = 0.f;
#pragma unroll
    for (int hh = 0; hh < 8; hh++)
        if (mh == hh) { iv = invd[hh]; sl = selfl[hh]; }
    float admh = __shfl_sync(0xffffffffu, adl, mh);

    float a0, a1, a2, a3;
    {
        float wgt = __expf(sl) * iv;  // self loop
        float4 v = *reinterpret_cast<const float4*>(&g_hw[(size_t)n * 128 + c0]);
        a0 = v.x * wgt; a1 = v.y * wgt; a2 = v.z * wgt; a3 = v.w * wgt;
    }
    for (int i = beg; i < end; i++) {
        int s = g_csr[i];
        float t = lrelu(g_as[s * 8 + mh] + admh);
        float wgt = __expf(t) * iv;
        float4 v = *reinterpret_cast<const float4*>(&g_hw[(size_t)s * 128 + c0]);
        a0 = fmaf(v.x, wgt, a0);
        a1 = fmaf(v.y, wgt, a1);
        a2 = fmaf(v.z, wgt, a2);
        a3 = fmaf(v.w, wgt, a3);
    }
    // epilogue: + gat bias, relu, + residual, LayerNorm
    float4 b4 = *reinterpret_cast<const float4*>(&gb[c0]);
    float v0 = fmaxf(a0 + b4.x, 0.f), v1 = fmaxf(a1 + b4.y, 0.f);
    float v2 = fmaxf(a2 + b4.z, 0.f), v3 = fmaxf(a3 + b4.w, 0.f);
    float4 r4 = *reinterpret_cast<const float4*>(&g_h[(size_t)n * 128 + c0]);
    v0 += r4.x; v1 += r4.y; v2 += r4.z; v3 += r4.w;
    float s1 = v0 + v1 + v2 + v3;
    float s2 = v0 * v0 + v1 * v1 + v2 * v2 + v3 * v3;
#pragma unroll
    for (int off = 16; off; off >>= 1) {
        s1 += __shfl_xor_sync(0xffffffffu, s1, off);
        s2 += __shfl_xor_sync(0xffffffffu, s2, off);
    }
    float mu = s1 * (1.f / 128.f);
    float var = s2 * (1.f / 128.f) - mu * mu;
    float rstd = rsqrtf(fmaxf(var, 0.f) + 1e-5f);
    float4 g4 = *reinterpret_cast<const float4*>(&lng[c0]);
    float4 bb4 = *reinterpret_cast<const float4*>(&lnb[c0]);
    float4 o;
    o.x = (v0 - mu) * rstd * g4.x + bb4.x;
    o.y = (v1 - mu) * rstd * g4.y + bb4.y;
    o.z = (v2 - mu) * rstd * g4.z + bb4.z;
    o.w = (v3 - mu) * rstd * g4.w + bb4.w;
    *reinterpret_cast<float4*>(&g_h[(size_t)n * 128 + c0]) = o;
}

// ---------------- MLP head final: out = t2 @ W3 + b3 ------------------------
__global__ void head_kernel(const float* __restrict__ W3,
                            const float* __restrict__ b3,
                            float* __restrict__ out) {
    int w = (blockIdx.x * blockDim.x + threadIdx.x) >> 5;
    int lane = threadIdx.x & 31;
    if (w >= NN) return;
    float2 a = *reinterpret_cast<const float2*>(&g_h[(size_t)w * 64 + lane * 2]);
    float2 wv = *reinterpret_cast<const float2*>(&W3[lane * 2]);
    float s = a.x * wv.x + a.y * wv.y;
#pragma unroll
    for (int off = 16; off; off >>= 1) s += __shfl_xor_sync(0xffffffffu, s, off);
    if (lane == 0) out[w] = s + b3[0];
}

// ---------------- launch ----------------------------------------------------
extern "C" void kernel_launch(void* const* d_in, const int* in_sizes, int n_in,
                              void* d_out, int out_size) {
    const float* x = (const float*)d_in[0];
    const int* ei = (const int*)d_in[1];
    const int* src = ei;
    const int* dst = ei + EE;
    const float* W_in = (const float*)d_in[3];
    const float* b_in = (const float*)d_in[4];
    float* out = (float*)d_out;

    float *p_h = nullptr, *p_hw = nullptr;
    int* p_cnt = nullptr;
    cudaGetSymbolAddress((void**)&p_h, g_h);
    cudaGetSymbolAddress((void**)&p_hw, g_hw);
    cudaGetSymbolAddress((void**)&p_cnt, g_cnt);

    const int SMEM_GEMM = (16384 + 8192) * 4;  // 96 KB
    cudaFuncSetAttribute(mma_gemm<0>, cudaFuncAttributeMaxDynamicSharedMemorySize, SMEM_GEMM);
    cudaFuncSetAttribute(mma_gemm<1>, cudaFuncAttributeMaxDynamicSharedMemorySize, SMEM_GEMM);
    const int NCTA = (NN + 127) / 128;  // 391

    input_proj<<<(NN * HH + 255) / 256, 256>>>(x, W_in, b_in);

    cudaMemsetAsync(p_cnt, 0, NN * sizeof(int));
    count_kernel<<<(EE + 255) / 256, 256>>>(dst);
    scan1<<<(NN + 511) / 512, 512>>>();
    scan2<<<1, 128>>>((NN + 511) / 512);
    scan3<<<(NN + 255) / 256, 256>>>();
    scatter<<<(EE + 255) / 256, 256>>>(src, dst);

    for (int l = 0; l < 3; l++) {
        const float* W  = (const float*)d_in[5 + 6 * l];
        const float* as = (const float*)d_in[6 + 6 * l];
        const float* ad = (const float*)d_in[7 + 6 * l];
        const float* gb = (const float*)d_in[8 + 6 * l];
        const float* lg = (const float*)d_in[9 + 6 * l];
        const float* lb = (const float*)d_in[10 + 6 * l];
        mma_gemm<0><<<dim3(NCTA, 2), 256, SMEM_GEMM>>>(p_h, W, 128, as, ad, p_hw, NN);
        aggregate_kernel<<<(NN + 7) / 8, 256>>>(gb, lg, lb);
    }
    // MLP head
    mma_gemm<1><<<dim3(NCTA, 2), 256, SMEM_GEMM>>>(p_h, (const float*)d_in[23], 128,
                                                   (const float*)d_in[24], nullptr, p_hw, NN);
    mma_gemm<1><<<dim3(NCTA, 1), 256, SMEM_GEMM>>>(p_hw, (const float*)d_in[25], 64,
                                                   (const float*)d_in[26], nullptr, p_h, NN);
    head_kernel<<<(NN * 32 + 255) / 256, 256>>>((const float*)d_in[27],
                                                (const float*)d_in[28], out);
}